// round 5
// baseline (speedup 1.0000x reference)
#include <cuda_runtime.h>
#include <cuda_fp16.h>
#include <math.h>

#define B  32
#define S  2048
#define D  64
#define R  4
#define NB 32

// ---------------- scratch (device globals; no allocation) ----------------
__device__ int    g_bucket[B*R*S];            // 1 MB
__device__ int    g_sortidx[B*R*S];           // 1 MB
__device__ float  g_qninv[B*S];               // 256 KB
__device__ __half g_att[(size_t)B*S*R*D];     // 32 MB  [b][t][r][d]
__device__ float  g_lse[B*S*R];               // 1 MB   [b][t][r]

// ---------------- mma / cp.async helpers ---------------------------------
__device__ __forceinline__ void mma_tf32(float* c,
                                         unsigned a0, unsigned a1, unsigned a2, unsigned a3,
                                         unsigned b0, unsigned b1)
{
    asm volatile(
        "mma.sync.aligned.m16n8k8.row.col.f32.tf32.tf32.f32 "
        "{%0,%1,%2,%3}, {%4,%5,%6,%7}, {%8,%9}, {%0,%1,%2,%3};"
        : "+f"(c[0]), "+f"(c[1]), "+f"(c[2]), "+f"(c[3])
        : "r"(a0), "r"(a1), "r"(a2), "r"(a3), "r"(b0), "r"(b1));
}

__device__ __forceinline__ void cpa16(unsigned dst, const float* src) {
    asm volatile("cp.async.cg.shared.global [%0], [%1], 16;" :: "r"(dst), "l"(src));
}
__device__ __forceinline__ void cpa_commit() {
    asm volatile("cp.async.commit_group;");
}
__device__ __forceinline__ void cpa_wait1() {
    asm volatile("cp.async.wait_group 1;");
}
__device__ __forceinline__ void cpa_wait0() {
    asm volatile("cp.async.wait_group 0;");
}

// ---------------- kernel 1: hash projection + bucket + key norm ----------
#define SQ_STR 68
#define HASH_SMEM (128*SQ_STR*4 + 64*64*4)   // sQ[128][68] + sR[64][64]

__global__ void __launch_bounds__(128) hash_kernel(const float* __restrict__ query,
                                                   const float* __restrict__ randm)
{
    extern __shared__ float hs[];
    float* sQ = hs;                 // [128][68]
    float* sR = hs + 128*SQ_STR;    // [64][64]  d-major, rk = r*16+k
    const int b   = blockIdx.y;
    const int tid = threadIdx.x;

    for (int i = tid; i < 1024; i += 128)
        *(float4*)&sR[i*4] = *(const float4*)&randm[b*4096 + i*4];
    const size_t qbase = ((size_t)b*S + (size_t)blockIdx.x*128)*D;
    for (int i = tid; i < 2048; i += 128) {           // coalesced float4
        float4 v = *(const float4*)&query[qbase + (size_t)i*4];
        int row = i >> 4, d4 = (i & 15) << 2;
        *(float4*)&sQ[row*SQ_STR + d4] = v;
    }
    __syncthreads();

    const int t = blockIdx.x*128 + tid;
    const float* q = &sQ[tid*SQ_STR];

    float acc[64];
#pragma unroll
    for (int i = 0; i < 64; i++) acc[i] = 0.f;
    float nrm = 0.f;
    for (int d = 0; d < D; d++) {
        float qd = q[d];
        nrm += qd*qd;
        const float4* rr = (const float4*)&sR[d*64];
#pragma unroll
        for (int i4 = 0; i4 < 16; i4++) {
            float4 r4 = rr[i4];
            acc[i4*4+0] += qd * r4.x;
            acc[i4*4+1] += qd * r4.y;
            acc[i4*4+2] += qd * r4.z;
            acc[i4*4+3] += qd * r4.w;
        }
    }
    g_qninv[b*S + t] = rsqrtf(fmaxf(nrm, 1e-12f));

#pragma unroll
    for (int r = 0; r < R; r++) {
        float bv = acc[r*16];
        int   bi = 0;
#pragma unroll
        for (int k = 1; k < 16; k++) {
            float v = acc[r*16 + k];
            if (v > bv) { bv = v; bi = k; }
        }
#pragma unroll
        for (int k = 0; k < 16; k++) {
            float v = -acc[r*16 + k];
            if (v > bv) { bv = v; bi = 16 + k; }
        }
        g_bucket[(b*R + r)*S + t] = bi;
    }
}

// ---------------- kernel 2: stable counting sort per (b, r) --------------
__global__ void sort_kernel()
{
    __shared__ int hist[NB*256];   // bucket-major, thread-minor
    __shared__ int wtot[8];
    const int br  = blockIdx.x;
    const int tid = threadIdx.x;
    const int* bk = g_bucket  + br*S;
    int*     sidx = g_sortidx + br*S;

    for (int i = tid; i < NB*256; i += 256) hist[i] = 0;
    __syncthreads();

    const int base = tid*8;
    int myb[8];
#pragma unroll
    for (int k = 0; k < 8; k++) { myb[k] = bk[base + k]; hist[myb[k]*256 + tid]++; }
    __syncthreads();

    // exclusive scan over 8192 entries in index order (stable)
    int run = 0;
    for (int i = tid*32; i < tid*32 + 32; i++) { int v = hist[i]; hist[i] = run; run += v; }
    const int lane = tid & 31, wid = tid >> 5;
    int x = run;
#pragma unroll
    for (int off = 1; off < 32; off <<= 1) {
        int nv = __shfl_up_sync(0xffffffffu, x, off);
        if (lane >= off) x += nv;
    }
    if (lane == 31) wtot[wid] = x;
    __syncthreads();
    if (tid < 8) {
        int y = wtot[tid], z = y;
#pragma unroll
        for (int off = 1; off < 8; off <<= 1) {
            int nv = __shfl_up_sync(0x000000ffu, z, off);
            if (tid >= off) z += nv;
        }
        wtot[tid] = z - y;    // exclusive warp offsets
    }
    __syncthreads();
    const int add = (x - run) + wtot[wid];
    for (int i = tid*32; i < tid*32 + 32; i++) hist[i] += add;
    __syncthreads();

#pragma unroll
    for (int k = 0; k < 8; k++) {
        int bb  = myb[k];
        int rnk = hist[bb*256 + tid]++;
        sidx[rnk] = base + k;
    }
}

// ---------------- kernel 3: bucketed attention, tf32 + pipelined loads ---
// smem layout (bytes):
//   [0,2048)          kiS   : int[512]         window key positions, per round
//   [2048,4096)       cinvS : float[512]       1/duplicate-count
//   [4096,6144)       scS   : float[512]       per-key qn*0.125 scale
//   [6144,7168)       statS : float2[64][2]    per-row (m,s) per warp-half
//   [7168,41984)      ksA   : float[128][68]   K window tile (rows 64.. = Q)
//   [41984,78848)     vs    : float[128][72]   V tile
//   [78848,112640)    ps    : float[64][132]   P matrix (cnt aliases, phase 0)
#define KS_STR 68
#define VS_STR 72
#define PS_STR 132
#define OFF_KI    0
#define OFF_CINV  2048
#define OFF_SC    4096
#define OFF_STATS 6144
#define OFF_KS    7168
#define OFF_VS    41984
#define OFF_PS    78848
#define ATTN_SMEM 112640

__global__ void __launch_bounds__(256) attn_kernel(const float* __restrict__ query,
                                                   const float* __restrict__ value)
{
    extern __shared__ char smem[];
    int*    kiS   = (int*)   (smem + OFF_KI);
    float*  cinvS = (float*) (smem + OFF_CINV);
    float*  scS   = (float*) (smem + OFF_SC);
    float2* statS = (float2*)(smem + OFF_STATS);
    float*  ksA   = (float*) (smem + OFF_KS);
    float*  vs    = (float*) (smem + OFF_VS);
    float*  ps    = (float*) (smem + OFF_PS);
    int*    cnt   = (int*)   (smem + OFF_PS);   // alias (phase 0 only)

    const int blk = blockIdx.x;
    const int b   = blk >> 5;
    const int n   = blk & 31;
    const int tid = threadIdx.x;
    const int l   = tid & 31;
    const int w   = tid >> 5;
    const int mi  = w & 3;     // m-tile (16 rows)
    const int nh  = w >> 2;    // n-half (64 cols)

    const int* sidx_b = g_sortidx + b*R*S;
    const int  prev   = (n + 31) & 31;
    const float* qn   = g_qninv + b*S;
    const float* Q    = query + (size_t)b*S*D;
    const float* V    = value + (size_t)b*S*D;

    const unsigned ks_s = (unsigned)__cvta_generic_to_shared(ksA);
    const unsigned vs_s = (unsigned)__cvta_generic_to_shared(vs);
    const int i0 = mi*16 + (l>>2);

    // ---- phase 0a: window key positions ----
    for (int idx = tid; idx < 512; idx += 256) {
        int r = idx >> 7, j = idx & 127;
        int slot = (j < 64) ? (prev*64 + j) : (n*64 + j - 64);
        kiS[idx] = sidx_b[r*S + slot];
    }
    __syncthreads();

    // ---- prologue: start round-0 loads (overlap with counting) ----
    {
        const int* ki = kiS;   // r = 0
#pragma unroll
        for (int it = 0; it < 8; it++) {
            int idx = it*256 + tid, row = idx >> 4, c4 = (idx & 15) << 2;
            cpa16(ks_s + (unsigned)(row*KS_STR + c4)*4, &Q[(size_t)ki[row]*D + c4]);
        }
        cpa_commit();
#pragma unroll
        for (int it = 0; it < 8; it++) {
            int idx = it*256 + tid, row = idx >> 4, c4 = (idx & 15) << 2;
            cpa16(vs_s + (unsigned)(row*VS_STR + c4)*4, &V[(size_t)ki[row]*D + c4]);
        }
        cpa_commit();
    }

    // ---- phase 0b: multiplicity counts + scales (cnt lives in ps) ----
    for (int idx = tid; idx < 2048; idx += 256) cnt[idx] = 0;
    __syncthreads();
    for (int idx = tid; idx < 512; idx += 256) atomicAdd(&cnt[kiS[idx]], 1);
    __syncthreads();
    for (int idx = tid; idx < 512; idx += 256) {
        int kp = kiS[idx];
        cinvS[idx] = 1.f / (float)cnt[kp];
        scS[idx]   = qn[kp] * 0.125f;
    }

    for (int r = 0; r < R; r++) {
        const int* ki = kiS + r*128;

        // ---- K(r) ready (oldest outstanding group) ----
        cpa_wait1();
        __syncthreads();

        // ---- GEMM1: S[64x128] = Q(rows 64..127 of ksA) . K^T ----
        float acc[8][4];
#pragma unroll
        for (int t2 = 0; t2 < 8; t2++)
#pragma unroll
            for (int c = 0; c < 4; c++) acc[t2][c] = 0.f;

        const float* Ab = ksA + (64 + i0)*KS_STR + (l&3);
        const float* Bb = ksA + (nh*64 + (l>>2))*KS_STR + (l&3);
#pragma unroll
        for (int kk = 0; kk < 8; kk++) {
            unsigned a0 = __float_as_uint(Ab[kk*8]);
            unsigned a1 = __float_as_uint(Ab[8*KS_STR + kk*8]);
            unsigned a2 = __float_as_uint(Ab[kk*8 + 4]);
            unsigned a3 = __float_as_uint(Ab[8*KS_STR + kk*8 + 4]);
#pragma unroll
            for (int nt = 0; nt < 8; nt++) {
                unsigned b0 = __float_as_uint(Bb[nt*8*KS_STR + kk*8]);
                unsigned b1 = __float_as_uint(Bb[nt*8*KS_STR + kk*8 + 4]);
                mma_tf32(acc[nt], a0, a1, a2, a3, b0, b1);
            }
        }

        // ---- in-register scale + masks + local softmax stats ----
        const int qpos0 = ki[64 + i0];
        const int qpos1 = ki[64 + i0 + 8];
        float m0 = -3.4e38f, m1 = -3.4e38f;
#pragma unroll
        for (int nt = 0; nt < 8; nt++) {
#pragma unroll
            for (int e = 0; e < 2; e++) {
                int col = nh*64 + nt*8 + 2*(l&3) + e;
                int kp  = ki[col];
                float sc = scS[r*128 + col];
                float x = acc[nt][e] * sc;
                if      (qpos0 <  kp) x = -1.0e9f;
                else if (qpos0 == kp) x = -1.0e5f;
                acc[nt][e] = x; m0 = fmaxf(m0, x);
                float y = acc[nt][2+e] * sc;
                if      (qpos1 <  kp) y = -1.0e9f;
                else if (qpos1 == kp) y = -1.0e5f;
                acc[nt][2+e] = y; m1 = fmaxf(m1, y);
            }
        }
        m0 = fmaxf(m0, __shfl_xor_sync(0xffffffffu, m0, 1));
        m0 = fmaxf(m0, __shfl_xor_sync(0xffffffffu, m0, 2));
        m1 = fmaxf(m1, __shfl_xor_sync(0xffffffffu, m1, 1));
        m1 = fmaxf(m1, __shfl_xor_sync(0xffffffffu, m1, 2));
        float s0 = 0.f, s1 = 0.f;
#pragma unroll
        for (int nt = 0; nt < 8; nt++)
#pragma unroll
            for (int e = 0; e < 2; e++) {
                float ex = __expf(acc[nt][e]   - m0); acc[nt][e]   = ex; s0 += ex;
                float ey = __expf(acc[nt][2+e] - m1); acc[nt][2+e] = ey; s1 += ey;
            }
        s0 += __shfl_xor_sync(0xffffffffu, s0, 1);
        s0 += __shfl_xor_sync(0xffffffffu, s0, 2);
        s1 += __shfl_xor_sync(0xffffffffu, s1, 1);
        s1 += __shfl_xor_sync(0xffffffffu, s1, 2);
        if ((l & 3) == 0) {
            statS[i0*2 + nh]       = make_float2(m0, s0);
            statS[(i0 + 8)*2 + nh] = make_float2(m1, s1);
        }
        __syncthreads();   // stats visible; all GEMM1 ksA reads done

        // ---- prefetch K(r+1) into ksA (overlaps softmax tail + GEMM2) ----
        if (r < R-1) {
            const int* kin = kiS + (r+1)*128;
#pragma unroll
            for (int it = 0; it < 8; it++) {
                int idx = it*256 + tid, row = idx >> 4, c4 = (idx & 15) << 2;
                cpa16(ks_s + (unsigned)(row*KS_STR + c4)*4, &Q[(size_t)kin[row]*D + c4]);
            }
            cpa_commit();
        }

        float2 ha = statS[i0*2],       hb = statS[i0*2 + 1];
        float M0 = fmaxf(ha.x, hb.x);
        float S0 = ha.y*__expf(ha.x - M0) + hb.y*__expf(hb.x - M0);
        float2 hc = statS[(i0+8)*2],   hd = statS[(i0+8)*2 + 1];
        float M1 = fmaxf(hc.x, hd.x);
        float S1 = hc.y*__expf(hc.x - M1) + hd.y*__expf(hd.x - M1);
        const float f0 = __expf(m0 - M0) / S0;
        const float f1 = __expf(m1 - M1) / S1;

#pragma unroll
        for (int nt = 0; nt < 8; nt++) {
            int col0 = nh*64 + nt*8 + 2*(l&3);
            float ci0 = cinvS[r*128 + col0], ci1 = cinvS[r*128 + col0 + 1];
            *(float2*)&ps[i0*PS_STR + col0] =
                make_float2(acc[nt][0]*f0*ci0, acc[nt][1]*f0*ci1);
            *(float2*)&ps[(i0+8)*PS_STR + col0] =
                make_float2(acc[nt][2]*f1*ci0, acc[nt][3]*f1*ci1);
        }
        if (((l & 3) == 0) && nh == 0) {
            g_lse[((size_t)b*S + qpos0)*R + r] = M0 + __logf(S0);
            g_lse[((size_t)b*S + qpos1)*R + r] = M1 + __logf(S1);
        }

        // ---- V(r) ready (oldest outstanding group) ----
        if (r < R-1) cpa_wait1(); else cpa_wait0();
        __syncthreads();   // ps + vs visible to all

        // ---- GEMM2: O[64x64] = P(64x128) . V ----
        float acc2[4][4];
#pragma unroll
        for (int t2 = 0; t2 < 4; t2++)
#pragma unroll
            for (int c = 0; c < 4; c++) acc2[t2][c] = 0.f;

        const float* Ab2 = ps + i0*PS_STR + (l&3);
        const float* Bb2 = vs + (l&3)*VS_STR + nh*32 + (l>>2);
#pragma unroll
        for (int kk = 0; kk < 16; kk++) {
            unsigned a0 = __float_as_uint(Ab2[kk*8]);
            unsigned a1 = __float_as_uint(Ab2[8*PS_STR + kk*8]);
            unsigned a2 = __float_as_uint(Ab2[kk*8 + 4]);
            unsigned a3 = __float_as_uint(Ab2[8*PS_STR + kk*8 + 4]);
#pragma unroll
            for (int nt = 0; nt < 4; nt++) {
                unsigned b0 = __float_as_uint(Bb2[(kk*8)*VS_STR + nt*8]);
                unsigned b1 = __float_as_uint(Bb2[(kk*8 + 4)*VS_STR + nt*8]);
                mma_tf32(acc2[nt], a0, a1, a2, a3, b0, b1);
            }
        }

        __half* o0 = g_att + (((size_t)b*S + qpos0)*R + r)*D;
        __half* o1 = g_att + (((size_t)b*S + qpos1)*R + r)*D;
#pragma unroll
        for (int nt = 0; nt < 4; nt++) {
            int d0 = nh*32 + nt*8 + 2*(l&3);
            *(__half2*)&o0[d0] = __floats2half2_rn(acc2[nt][0], acc2[nt][1]);
            *(__half2*)&o1[d0] = __floats2half2_rn(acc2[nt][2], acc2[nt][3]);
        }
        __syncthreads();   // all vs reads done

        // ---- prefetch V(r+1) into vs (overlaps next round's GEMM1) ----
        if (r < R-1) {
            const int* kin = kiS + (r+1)*128;
#pragma unroll
            for (int it = 0; it < 8; it++) {
                int idx = it*256 + tid, row = idx >> 4, c4 = (idx & 15) << 2;
                cpa16(vs_s + (unsigned)(row*VS_STR + c4)*4, &V[(size_t)kin[row]*D + c4]);
            }
            cpa_commit();
        }
    }
}

// ---------------- kernel 4: combine (warp per row, 16B transactions) -----
__global__ void __launch_bounds__(256) combine_kernel(float* __restrict__ out)
{
    const int tid = threadIdx.x;
    const int l   = tid & 31;
    const int row = blockIdx.x*8 + (tid >> 5);      // b*S + t
    const float* lp = g_lse + (size_t)row*R;
    float l0 = lp[0], l1 = lp[1], l2 = lp[2], l3 = lp[3];
    float m  = fmaxf(fmaxf(l0, l1), fmaxf(l2, l3));
    float w0 = __expf(l0 - m), w1 = __expf(l1 - m);
    float w2 = __expf(l2 - m), w3 = __expf(l3 - m);
    float inv = 1.f / (w0 + w1 + w2 + w3);
    const int r = l >> 3;
    float wsel = ((r == 0) ? w0 : (r == 1) ? w1 : (r == 2) ? w2 : w3) * inv;

    // lane l: 8 halves = round r, dims (l&7)*8 .. +7
    uint4 raw = *(const uint4*)((const char*)(g_att + (size_t)row*R*D) + l*16);
    const __half2* h = (const __half2*)&raw;
    float acc[8];
#pragma unroll
    for (int j = 0; j < 4; j++) {
        float2 f = __half22float2(h[j]);
        acc[2*j]   = f.x * wsel;
        acc[2*j+1] = f.y * wsel;
    }
#pragma unroll
    for (int j = 0; j < 8; j++) {
        acc[j] += __shfl_xor_sync(0xffffffffu, acc[j], 8);
        acc[j] += __shfl_xor_sync(0xffffffffu, acc[j], 16);
    }
    float* o = &out[(size_t)row*D + (l & 7)*8];
    if (l < 8)
        *(float4*)o       = make_float4(acc[0], acc[1], acc[2], acc[3]);
    else if (l < 16)
        *(float4*)(o + 4) = make_float4(acc[4], acc[5], acc[6], acc[7]);
}

// ---------------- launch --------------------------------------------------
extern "C" void kernel_launch(void* const* d_in, const int* in_sizes, int n_in,
                              void* d_out, int out_size)
{
    const float* query = (const float*)d_in[0];
    const float* value = (const float*)d_in[1];
    const float* randm = (const float*)d_in[2];
    float* out = (float*)d_out;

    cudaFuncSetAttribute(hash_kernel,
                         cudaFuncAttributeMaxDynamicSharedMemorySize, HASH_SMEM);
    cudaFuncSetAttribute(attn_kernel,
                         cudaFuncAttributeMaxDynamicSharedMemorySize, ATTN_SMEM);

    hash_kernel<<<dim3(S/128, B), 128, HASH_SMEM>>>(query, randm);
    sort_kernel<<<B*R, 256>>>();
    attn_kernel<<<B*NB, 256, ATTN_SMEM>>>(query, value);
    combine_kernel<<<(B*S)/8, 256>>>(out);
}

// round 8
// speedup vs baseline: 1.0262x; 1.0262x over previous
#include <cuda_runtime.h>
#include <cuda_fp16.h>
#include <math.h>

#define B  32
#define S  2048
#define D  64
#define R  4
#define NB 32

// ---------------- scratch (device globals; no allocation) ----------------
__device__ int    g_bucket[B*R*S];            // 1 MB
__device__ int    g_sortidx[B*R*S];           // 1 MB
__device__ float  g_qninv[B*S];               // 256 KB
__device__ __half g_att[(size_t)B*S*R*D];     // 32 MB  [b][t][r][d]
__device__ float  g_lse[B*S*R];               // 1 MB   [b][t][r]

// ---------------- mma / cp.async / ldmatrix helpers ----------------------
__device__ __forceinline__ void mma_tf32(float* c,
                                         unsigned a0, unsigned a1, unsigned a2, unsigned a3,
                                         unsigned b0, unsigned b1)
{
    asm volatile(
        "mma.sync.aligned.m16n8k8.row.col.f32.tf32.tf32.f32 "
        "{%0,%1,%2,%3}, {%4,%5,%6,%7}, {%8,%9}, {%0,%1,%2,%3};"
        : "+f"(c[0]), "+f"(c[1]), "+f"(c[2]), "+f"(c[3])
        : "r"(a0), "r"(a1), "r"(a2), "r"(a3), "r"(b0), "r"(b1));
}

// 4x m8n8.b16 matrices; on tf32 tiles stored [row][4B-elem] this yields the
// exact a0..a3 / b0,b1 lane mapping of m16n8k8.row.col (derivation in header).
__device__ __forceinline__ void ldsm4(unsigned& r0, unsigned& r1,
                                      unsigned& r2, unsigned& r3, unsigned addr)
{
    asm volatile("ldmatrix.sync.aligned.m8n8.x4.shared.b16 {%0,%1,%2,%3}, [%4];"
                 : "=r"(r0), "=r"(r1), "=r"(r2), "=r"(r3) : "r"(addr));
}

__device__ __forceinline__ void cpa16(unsigned dst, const float* src) {
    asm volatile("cp.async.cg.shared.global [%0], [%1], 16;" :: "r"(dst), "l"(src));
}
__device__ __forceinline__ void cpa_commit() { asm volatile("cp.async.commit_group;"); }
__device__ __forceinline__ void cpa_wait1()  { asm volatile("cp.async.wait_group 1;"); }
__device__ __forceinline__ void cpa_wait0()  { asm volatile("cp.async.wait_group 0;"); }

// ---------------- kernel 1: hash projection + bucket + key norm ----------
#define SQ_STR 68
#define HASH_SMEM (128*SQ_STR*4 + 64*64*4)   // sQ[128][68] + sR[64][64]

__global__ void __launch_bounds__(128) hash_kernel(const float* __restrict__ query,
                                                   const float* __restrict__ randm)
{
    extern __shared__ float hs[];
    float* sQ = hs;                 // [128][68]
    float* sR = hs + 128*SQ_STR;    // [64][64]  d-major, rk = r*16+k
    const int b   = blockIdx.y;
    const int tid = threadIdx.x;

    for (int i = tid; i < 1024; i += 128)
        *(float4*)&sR[i*4] = *(const float4*)&randm[b*4096 + i*4];
    const size_t qbase = ((size_t)b*S + (size_t)blockIdx.x*128)*D;
    for (int i = tid; i < 2048; i += 128) {           // coalesced float4
        float4 v = *(const float4*)&query[qbase + (size_t)i*4];
        int row = i >> 4, d4 = (i & 15) << 2;
        *(float4*)&sQ[row*SQ_STR + d4] = v;
    }
    __syncthreads();

    const int t = blockIdx.x*128 + tid;
    const float* q = &sQ[tid*SQ_STR];

    float acc[64];
#pragma unroll
    for (int i = 0; i < 64; i++) acc[i] = 0.f;
    float nrm = 0.f;
    for (int d = 0; d < D; d++) {
        float qd = q[d];
        nrm += qd*qd;
        const float4* rr = (const float4*)&sR[d*64];
#pragma unroll
        for (int i4 = 0; i4 < 16; i4++) {
            float4 r4 = rr[i4];
            acc[i4*4+0] += qd * r4.x;
            acc[i4*4+1] += qd * r4.y;
            acc[i4*4+2] += qd * r4.z;
            acc[i4*4+3] += qd * r4.w;
        }
    }
    g_qninv[b*S + t] = rsqrtf(fmaxf(nrm, 1e-12f));

#pragma unroll
    for (int r = 0; r < R; r++) {
        float bv = acc[r*16];
        int   bi = 0;
#pragma unroll
        for (int k = 1; k < 16; k++) {
            float v = acc[r*16 + k];
            if (v > bv) { bv = v; bi = k; }
        }
#pragma unroll
        for (int k = 0; k < 16; k++) {
            float v = -acc[r*16 + k];
            if (v > bv) { bv = v; bi = 16 + k; }
        }
        g_bucket[(b*R + r)*S + t] = bi;
    }
}

// ---------------- kernel 2: stable counting sort per (b, r) --------------
__global__ void sort_kernel()
{
    __shared__ int hist[NB*256];   // bucket-major, thread-minor
    __shared__ int wtot[8];
    const int br  = blockIdx.x;
    const int tid = threadIdx.x;
    const int* bk = g_bucket  + br*S;
    int*     sidx = g_sortidx + br*S;

    for (int i = tid; i < NB*256; i += 256) hist[i] = 0;
    __syncthreads();

    const int base = tid*8;
    int myb[8];
#pragma unroll
    for (int k = 0; k < 8; k++) { myb[k] = bk[base + k]; hist[myb[k]*256 + tid]++; }
    __syncthreads();

    // exclusive scan over 8192 entries in index order (stable)
    int run = 0;
    for (int i = tid*32; i < tid*32 + 32; i++) { int v = hist[i]; hist[i] = run; run += v; }
    const int lane = tid & 31, wid = tid >> 5;
    int x = run;
#pragma unroll
    for (int off = 1; off < 32; off <<= 1) {
        int nv = __shfl_up_sync(0xffffffffu, x, off);
        if (lane >= off) x += nv;
    }
    if (lane == 31) wtot[wid] = x;
    __syncthreads();
    if (tid < 8) {
        int y = wtot[tid], z = y;
#pragma unroll
        for (int off = 1; off < 8; off <<= 1) {
            int nv = __shfl_up_sync(0x000000ffu, z, off);
            if (tid >= off) z += nv;
        }
        wtot[tid] = z - y;    // exclusive warp offsets
    }
    __syncthreads();
    const int add = (x - run) + wtot[wid];
    for (int i = tid*32; i < tid*32 + 32; i++) hist[i] += add;
    __syncthreads();

#pragma unroll
    for (int k = 0; k < 8; k++) {
        int bb  = myb[k];
        int rnk = hist[bb*256 + tid]++;
        sidx[rnk] = base + k;
    }
}

// ---------------- kernel 3: bucketed attention, tf32 + ldmatrix ----------
// smem layout (bytes):
//   [0,2048)          kiS   : int[512]         window key positions, per round
//   [2048,4096)       cinvS : float[512]       1/duplicate-count
//   [4096,6144)       scS   : float[512]       per-key qn*0.125 scale
//   [6144,7168)       statS : float2[64][2]    per-row (m,s) per warp-half
//   [7168,41984)      ksA   : float[128][68]   K window tile (rows 64.. = Q)
//   [41984,78848)     vs    : float[128][72]   V tile
//   [78848,112640)    ps    : float[64][132]   P matrix (cnt aliases, phase 0)
#define KS_STR 68
#define VS_STR 72
#define PS_STR 132
#define OFF_KI    0
#define OFF_CINV  2048
#define OFF_SC    4096
#define OFF_STATS 6144
#define OFF_KS    7168
#define OFF_VS    41984
#define OFF_PS    78848
#define ATTN_SMEM 112640

__global__ void __launch_bounds__(256) attn_kernel(const float* __restrict__ query,
                                                   const float* __restrict__ value)
{
    extern __shared__ char smem[];
    int*    kiS   = (int*)   (smem + OFF_KI);
    float*  cinvS = (float*) (smem + OFF_CINV);
    float*  scS   = (float*) (smem + OFF_SC);
    float2* statS = (float2*)(smem + OFF_STATS);
    float*  ksA   = (float*) (smem + OFF_KS);
    float*  vs    = (float*) (smem + OFF_VS);
    float*  ps    = (float*) (smem + OFF_PS);
    int*    cnt   = (int*)   (smem + OFF_PS);   // alias (phase 0 only)

    const int blk = blockIdx.x;
    const int b   = blk >> 5;
    const int n   = blk & 31;
    const int tid = threadIdx.x;
    const int l   = tid & 31;
    const int w   = tid >> 5;
    const int mi  = w & 3;     // m-tile (16 rows)
    const int nh  = w >> 2;    // n-half (64 cols)

    const int* sidx_b = g_sortidx + b*R*S;
    const int  prev   = (n + 31) & 31;
    const float* qn   = g_qninv + b*S;
    const float* Q    = query + (size_t)b*S*D;
    const float* V    = value + (size_t)b*S*D;

    const unsigned ks_s = (unsigned)__cvta_generic_to_shared(ksA);
    const unsigned vs_s = (unsigned)__cvta_generic_to_shared(vs);
    const unsigned ps_s = (unsigned)__cvta_generic_to_shared(ps);
    const int i0 = mi*16 + (l>>2);

    // per-lane ldmatrix base addresses (bytes)
    const int lrow = (l & 7) + ((l & 8) ? 8 : 0);     // row within 16-row frag
    const int lcol = (l & 16) ? 4 : 0;                // col half (tf32 elems)
    const unsigned aG1 = ks_s + (unsigned)((64 + mi*16 + lrow)*KS_STR + lcol)*4;
    const unsigned bG1 = ks_s + (unsigned)((nh*64 + (l & 7))*KS_STR + ((l >> 3) & 3)*4)*4;
    const unsigned aG2 = ps_s + (unsigned)((mi*16 + lrow)*PS_STR + lcol)*4;

    // ---- phase 0a: window key positions ----
    for (int idx = tid; idx < 512; idx += 256) {
        int r = idx >> 7, j = idx & 127;
        int slot = (j < 64) ? (prev*64 + j) : (n*64 + j - 64);
        kiS[idx] = sidx_b[r*S + slot];
    }
    __syncthreads();

    // ---- prologue: start round-0 loads (overlap with counting) ----
    {
        const int* ki = kiS;   // r = 0
#pragma unroll
        for (int it = 0; it < 8; it++) {
            int idx = it*256 + tid, row = idx >> 4, c4 = (idx & 15) << 2;
            cpa16(ks_s + (unsigned)(row*KS_STR + c4)*4, &Q[(size_t)ki[row]*D + c4]);
        }
        cpa_commit();
#pragma unroll
        for (int it = 0; it < 8; it++) {
            int idx = it*256 + tid, row = idx >> 4, c4 = (idx & 15) << 2;
            cpa16(vs_s + (unsigned)(row*VS_STR + c4)*4, &V[(size_t)ki[row]*D + c4]);
        }
        cpa_commit();
    }

    // ---- phase 0b: multiplicity counts + scales (cnt lives in ps) ----
    for (int idx = tid; idx < 2048; idx += 256) cnt[idx] = 0;
    __syncthreads();
    for (int idx = tid; idx < 512; idx += 256) atomicAdd(&cnt[kiS[idx]], 1);
    __syncthreads();
    for (int idx = tid; idx < 512; idx += 256) {
        int kp = kiS[idx];
        cinvS[idx] = 1.f / (float)cnt[kp];
        scS[idx]   = qn[kp] * 0.125f;
    }

    for (int r = 0; r < R; r++) {
        const int* ki = kiS + r*128;

        // ---- K(r) ready (oldest outstanding group) ----
        cpa_wait1();
        __syncthreads();

        // ---- GEMM1: S[64x128] = Q(rows 64..127 of ksA) . K^T ----
        float acc[8][4];
#pragma unroll
        for (int t2 = 0; t2 < 8; t2++)
#pragma unroll
            for (int c = 0; c < 4; c++) acc[t2][c] = 0.f;

#pragma unroll
        for (int kp = 0; kp < 4; kp++) {            // kk = 2kp, 2kp+1
            unsigned a0,a1,a2,a3, a4,a5,a6,a7;
            ldsm4(a0,a1,a2,a3, aG1 + kp*64);        // kk=2kp   (8 floats=32B)
            ldsm4(a4,a5,a6,a7, aG1 + kp*64 + 32);   // kk=2kp+1
#pragma unroll
            for (int nt = 0; nt < 8; nt++) {
                unsigned b0,b1,b2,b3;               // b0,b1 of kk ; b0,b1 of kk+1
                ldsm4(b0,b1,b2,b3, bG1 + (unsigned)(nt*8*KS_STR)*4 + kp*64);
                mma_tf32(acc[nt], a0,a1,a2,a3, b0,b1);
                mma_tf32(acc[nt], a4,a5,a6,a7, b2,b3);
            }
        }

        // ---- in-register scale + masks + local softmax stats ----
        const int qpos0 = ki[64 + i0];
        const int qpos1 = ki[64 + i0 + 8];
        float m0 = -3.4e38f, m1 = -3.4e38f;
#pragma unroll
        for (int nt = 0; nt < 8; nt++) {
#pragma unroll
            for (int e = 0; e < 2; e++) {
                int col = nh*64 + nt*8 + 2*(l&3) + e;
                int kp  = ki[col];
                float sc = scS[r*128 + col];
                float x = acc[nt][e] * sc;
                if      (qpos0 <  kp) x = -1.0e9f;
                else if (qpos0 == kp) x = -1.0e5f;
                acc[nt][e] = x; m0 = fmaxf(m0, x);
                float y = acc[nt][2+e] * sc;
                if      (qpos1 <  kp) y = -1.0e9f;
                else if (qpos1 == kp) y = -1.0e5f;
                acc[nt][2+e] = y; m1 = fmaxf(m1, y);
            }
        }
        m0 = fmaxf(m0, __shfl_xor_sync(0xffffffffu, m0, 1));
        m0 = fmaxf(m0, __shfl_xor_sync(0xffffffffu, m0, 2));
        m1 = fmaxf(m1, __shfl_xor_sync(0xffffffffu, m1, 1));
        m1 = fmaxf(m1, __shfl_xor_sync(0xffffffffu, m1, 2));
        float s0 = 0.f, s1 = 0.f;
#pragma unroll
        for (int nt = 0; nt < 8; nt++)
#pragma unroll
            for (int e = 0; e < 2; e++) {
                float ex = __expf(acc[nt][e]   - m0); acc[nt][e]   = ex; s0 += ex;
                float ey = __expf(acc[nt][2+e] - m1); acc[nt][2+e] = ey; s1 += ey;
            }
        s0 += __shfl_xor_sync(0xffffffffu, s0, 1);
        s0 += __shfl_xor_sync(0xffffffffu, s0, 2);
        s1 += __shfl_xor_sync(0xffffffffu, s1, 1);
        s1 += __shfl_xor_sync(0xffffffffu, s1, 2);
        if ((l & 3) == 0) {
            statS[i0*2 + nh]       = make_float2(m0, s0);
            statS[(i0 + 8)*2 + nh] = make_float2(m1, s1);
        }
        __syncthreads();   // stats visible; all GEMM1 ksA reads done

        // ---- prefetch K(r+1) into ksA (overlaps softmax tail + GEMM2) ----
        if (r < R-1) {
            const int* kin = kiS + (r+1)*128;
#pragma unroll
            for (int it = 0; it < 8; it++) {
                int idx = it*256 + tid, row = idx >> 4, c4 = (idx & 15) << 2;
                cpa16(ks_s + (unsigned)(row*KS_STR + c4)*4, &Q[(size_t)kin[row]*D + c4]);
            }
            cpa_commit();
        }

        float2 ha = statS[i0*2],       hb = statS[i0*2 + 1];
        float M0 = fmaxf(ha.x, hb.x);
        float S0 = ha.y*__expf(ha.x - M0) + hb.y*__expf(hb.x - M0);
        float2 hc = statS[(i0+8)*2],   hd = statS[(i0+8)*2 + 1];
        float M1 = fmaxf(hc.x, hd.x);
        float S1 = hc.y*__expf(hc.x - M1) + hd.y*__expf(hd.x - M1);
        const float f0 = __expf(m0 - M0) / S0;
        const float f1 = __expf(m1 - M1) / S1;

#pragma unroll
        for (int nt = 0; nt < 8; nt++) {
            int col0 = nh*64 + nt*8 + 2*(l&3);
            float ci0 = cinvS[r*128 + col0], ci1 = cinvS[r*128 + col0 + 1];
            *(float2*)&ps[i0*PS_STR + col0] =
                make_float2(acc[nt][0]*f0*ci0, acc[nt][1]*f0*ci1);
            *(float2*)&ps[(i0+8)*PS_STR + col0] =
                make_float2(acc[nt][2]*f1*ci0, acc[nt][3]*f1*ci1);
        }
        if (((l & 3) == 0) && nh == 0) {
            g_lse[((size_t)b*S + qpos0)*R + r] = M0 + __logf(S0);
            g_lse[((size_t)b*S + qpos1)*R + r] = M1 + __logf(S1);
        }

        // ---- V(r) ready (oldest outstanding group) ----
        if (r < R-1) cpa_wait1(); else cpa_wait0();
        __syncthreads();   // ps + vs visible to all

        // ---- GEMM2: O[64x64] = P(64x128) . V ----
        float acc2[4][4];
#pragma unroll
        for (int t2 = 0; t2 < 4; t2++)
#pragma unroll
            for (int c = 0; c < 4; c++) acc2[t2][c] = 0.f;

        const float* Bb2 = vs + (l&3)*VS_STR + nh*32 + (l>>2);
#pragma unroll
        for (int kp = 0; kp < 8; kp++) {            // kk = 2kp, 2kp+1
            unsigned a0,a1,a2,a3, a4,a5,a6,a7;
            ldsm4(a0,a1,a2,a3, aG2 + kp*64);
            ldsm4(a4,a5,a6,a7, aG2 + kp*64 + 32);
#pragma unroll
            for (int nt = 0; nt < 4; nt++) {
                unsigned b0 = __float_as_uint(Bb2[(kp*16    )*VS_STR + nt*8]);
                unsigned b1 = __float_as_uint(Bb2[(kp*16 + 4)*VS_STR + nt*8]);
                unsigned b2 = __float_as_uint(Bb2[(kp*16 + 8)*VS_STR + nt*8]);
                unsigned b3 = __float_as_uint(Bb2[(kp*16 +12)*VS_STR + nt*8]);
                mma_tf32(acc2[nt], a0,a1,a2,a3, b0,b1);
                mma_tf32(acc2[nt], a4,a5,a6,a7, b2,b3);
            }
        }

        __half* o0 = g_att + (((size_t)b*S + qpos0)*R + r)*D;
        __half* o1 = g_att + (((size_t)b*S + qpos1)*R + r)*D;
#pragma unroll
        for (int nt = 0; nt < 4; nt++) {
            int d0 = nh*32 + nt*8 + 2*(l&3);
            *(__half2*)&o0[d0] = __floats2half2_rn(acc2[nt][0], acc2[nt][1]);
            *(__half2*)&o1[d0] = __floats2half2_rn(acc2[nt][2], acc2[nt][3]);
        }
        __syncthreads();   // all vs reads done

        // ---- prefetch V(r+1) into vs (overlaps next round's GEMM1) ----
        if (r < R-1) {
            const int* kin = kiS + (r+1)*128;
#pragma unroll
            for (int it = 0; it < 8; it++) {
                int idx = it*256 + tid, row = idx >> 4, c4 = (idx & 15) << 2;
                cpa16(vs_s + (unsigned)(row*VS_STR + c4)*4, &V[(size_t)kin[row]*D + c4]);
            }
            cpa_commit();
        }
    }
}

// ---------------- kernel 4: per-position round combine (fp16 att) --------
__global__ void __launch_bounds__(256) combine_kernel(float* __restrict__ out)
{
    const int tid = threadIdx.x;
    const int d2  = tid & 31;                       // half2 index (2 dims)
    const int row = blockIdx.x*8 + (tid >> 5);      // b*S + t
    float4 lv = *(const float4*)(g_lse + (size_t)row*R);
    float m  = fmaxf(fmaxf(lv.x, lv.y), fmaxf(lv.z, lv.w));
    float w0 = __expf(lv.x - m), w1 = __expf(lv.y - m);
    float w2 = __expf(lv.z - m), w3 = __expf(lv.w - m);
    float inv = 1.f / (w0 + w1 + w2 + w3);
    const __half2* a = (const __half2*)g_att + (size_t)row*R*(D/2);
    float2 a0 = __half22float2(a[0*(D/2) + d2]);
    float2 a1 = __half22float2(a[1*(D/2) + d2]);
    float2 a2 = __half22float2(a[2*(D/2) + d2]);
    float2 a3 = __half22float2(a[3*(D/2) + d2]);
    float2 res;
    res.x = (a0.x*w0 + a1.x*w1 + a2.x*w2 + a3.x*w3) * inv;
    res.y = (a0.y*w0 + a1.y*w1 + a2.y*w2 + a3.y*w3) * inv;
    *(float2*)&out[(size_t)row*D + d2*2] = res;
}

// ---------------- launch --------------------------------------------------
extern "C" void kernel_launch(void* const* d_in, const int* in_sizes, int n_in,
                              void* d_out, int out_size)
{
    const float* query = (const float*)d_in[0];
    const float* value = (const float*)d_in[1];
    const float* randm = (const float*)d_in[2];
    float* out = (float*)d_out;

    cudaFuncSetAttribute(hash_kernel,
                         cudaFuncAttributeMaxDynamicSharedMemorySize, HASH_SMEM);
    cudaFuncSetAttribute(attn_kernel,
                         cudaFuncAttributeMaxDynamicSharedMemorySize, ATTN_SMEM);

    hash_kernel<<<dim3(S/128, B), 128, HASH_SMEM>>>(query, randm);
    sort_kernel<<<B*R, 256>>>();
    attn_kernel<<<B*NB, 256, ATTN_SMEM>>>(query, value);
    combine_kernel<<<(B*S)/8, 256>>>(out);
}